// round 11
// baseline (speedup 1.0000x reference)
#include <cuda_runtime.h>

// ---------------- problem constants ----------------
#define C_CH   256
#define C_HALF 128                 // channels per split-K half
#define H_BEV  200
#define W_BEV  704
#define HW     (H_BEV * W_BEV)     // 140800
#define A_NUM  2
#define NC_NUM 4
#define K_SEL  20000
#define NSLOT  (A_NUM * HW)        // 281600 flat A*H*W cells
#define RM_OFF NSLOT               // rm starts after psm in d_out
#define NOUT16 16                  // 2 cls + 14 reg channels
#define PX_PER_BLK 128             // pixels per block (256 threads, split=2)

// packed winner table: high32 = float bits of peer score (positive -> monotonic),
// low32 = ((3 - cav_idx) << 16) | k.  0 == no peer selected this cell.
__device__ __align__(16) unsigned long long g_slots[NSLOT];

// ---------------- f32x2 helpers ----------------
__device__ __forceinline__ unsigned long long pack2(float lo, float hi) {
    unsigned long long r;
    asm("mov.b64 %0, {%1, %2};" : "=l"(r) : "f"(lo), "f"(hi));
    return r;
}
__device__ __forceinline__ void unpack2(unsigned long long v, float& lo, float& hi) {
    asm("mov.b64 {%0, %1}, %2;" : "=f"(lo), "=f"(hi) : "l"(v));
}
__device__ __forceinline__ unsigned long long fma2(unsigned long long a,
                                                   unsigned long long b,
                                                   unsigned long long c) {
    asm("fma.rn.f32x2 %0, %1, %2, %3;" : "=l"(c) : "l"(a), "l"(b), "l"(c));
    return c;
}
__device__ __forceinline__ unsigned long long add2(unsigned long long a,
                                                   unsigned long long b) {
    unsigned long long r;
    asm("add.rn.f32x2 %0, %1, %2;" : "=l"(r) : "l"(a), "l"(b));
    return r;
}

// ---------------- kernel 1: scatter peer candidates ----------------
__global__ void k_scatter(const int* __restrict__ mask_idx,
                          const float* __restrict__ scores) {
    int t = blockIdx.x * blockDim.x + threadIdx.x;
    if (t >= NC_NUM * K_SEL) return;
    int i = t / K_SEL;
    int k = t - i * K_SEL;                       // k < 20000 < 2^16
    int f = mask_idx[t];                         // flat index in [0, A*H*W)
    unsigned long long key =
        ((unsigned long long)__float_as_uint(scores[t]) << 32) |
        ((unsigned long long)(3 - i) << 16) | (unsigned)k;
    atomicMax(&g_slots[f], key);
}

// ---------------- kernel 2: fused heads (split-K=2, 1 px/thread) -----------
// 256 threads = 128 pixels x 2 channel-halves.  1100 blocks exactly.
__global__ __launch_bounds__(256)
void k_main(const float*  __restrict__ feat,     // [C, HW] f32
            const float*  __restrict__ cls_w,    // [2, 256]
            const float*  __restrict__ cls_b,    // [2]
            const float*  __restrict__ reg_w,    // [14, 256]
            const float*  __restrict__ reg_b,    // [14]
            const float*  __restrict__ psm_v2x,  // [4, 20000]
            const float*  __restrict__ rm_v2x,   // [4, 7*20000]
            float*        __restrict__ out) {    // [psm 281600 | rm 1971200]
    // weights stored once as f32x2 output-pairs: w2v[c][g].x = (w_{4g},w_{4g+1}),
    // .y = (w_{4g+2},w_{4g+3}).  One broadcast LDS.128 feeds 4 outputs.
    __shared__ __align__(16) ulonglong2 w2v[C_CH][NOUT16 / 4];       // 16 KB
    // split-K partials from half 1: per-h planes, 8B-consecutive -> 0-conflict
    __shared__ __align__(16) unsigned long long red[NOUT16 / 2][PX_PER_BLK]; // 8 KB

    for (int idx = threadIdx.x; idx < C_CH * (NOUT16 / 2); idx += blockDim.x) {
        int c = idx >> 3, h = idx & 7;           // h = output-pair index 0..7
        int o0 = 2 * h, o1 = 2 * h + 1;
        float w0 = (o0 < A_NUM) ? cls_w[o0 * C_CH + c] : reg_w[(o0 - A_NUM) * C_CH + c];
        float w1 = (o1 < A_NUM) ? cls_w[o1 * C_CH + c] : reg_w[(o1 - A_NUM) * C_CH + c];
        ((unsigned long long*)&w2v[c][0])[h] = pack2(w0, w1);
    }
    __syncthreads();

    int px   = threadIdx.x & (PX_PER_BLK - 1);   // pixel slot in block
    int half = threadIdx.x >> 7;                 // channel half 0/1
    int p    = blockIdx.x * PX_PER_BLK + px;     // global pixel id
    int c0   = half * C_HALF;

    unsigned long long acc[NOUT16 / 2];          // 8 output-pairs (f32x2)
#pragma unroll
    for (int h = 0; h < NOUT16 / 2; ++h) acc[h] = 0ULL;

    const float* fp = feat + (size_t)c0 * HW + p;
    const ulonglong2* wp = &w2v[c0][0];
#pragma unroll 8
    for (int c = 0; c < C_HALF; ++c) {
        float x = *fp;                           // coalesced 4B (128B/warp)
        fp += HW;
        unsigned long long xs = pack2(x, x);     // splat pixel value
#pragma unroll
        for (int g = 0; g < NOUT16 / 4; ++g) {
            ulonglong2 w = wp[g];                // broadcast LDS.128
            acc[2 * g]     = fma2(xs, w.x, acc[2 * g]);
            acc[2 * g + 1] = fma2(xs, w.y, acc[2 * g + 1]);
        }
        wp += NOUT16 / 4;
    }

    // ---- split-K reduction: half 1 publishes, half 0 combines ----
    if (half == 1) {
#pragma unroll
        for (int h = 0; h < NOUT16 / 2; ++h)
            red[h][px] = acc[h];                 // STS.64 conflict-free
    }
    __syncthreads();
    if (half == 1) return;

#pragma unroll
    for (int h = 0; h < NOUT16 / 2; ++h)
        acc[h] = add2(acc[h], red[h][px]);

    float v[NOUT16];
#pragma unroll
    for (int h = 0; h < NOUT16 / 2; ++h)
        unpack2(acc[h], v[2 * h], v[2 * h + 1]);

#pragma unroll
    for (int a = 0; a < A_NUM; ++a) {
        int f = a * HW + p;
        float psm_ego = v[a] + cls_b[a];
        float prob    = 1.0f / (1.0f + expf(-psm_ego));      // sigmoid, fp32

        unsigned long long key = g_slots[f];                 // coalesced LDG.64
        bool peer = false;
        int ci = 0, ck = 0;
        if (key != 0ULL) {
            float s = __uint_as_float((unsigned)(key >> 32));
            if (s > prob) {                  // strict >: ego wins ties (argmax first-max)
                peer = true;
                unsigned lo = (unsigned)key;
                ck = (int)(lo & 0xFFFFu);
                ci = 3 - (int)((lo >> 16) & 0xFFFFu);
            }
        }

        out[f] = peer ? psm_v2x[ci * K_SEL + ck] : psm_ego;

#pragma unroll
        for (int r = 0; r < 7; ++r) {
            int rc = 2 * r + a;              // rm channel using anchor-a winner
            float ego = v[A_NUM + rc] + reg_b[rc];
            out[RM_OFF + rc * HW + p] =
                peer ? rm_v2x[(ci * 7 + r) * K_SEL + ck] : ego;
        }
    }
}

// ---------------- launch ----------------
extern "C" void kernel_launch(void* const* d_in, const int* in_sizes, int n_in,
                              void* d_out, int out_size) {
    const float*  feat     = (const float*)d_in[0];   // [1,256,200,704] f32
    const float*  cls_w    = (const float*)d_in[1];   // [2,256]
    const float*  cls_b    = (const float*)d_in[2];   // [2]
    const float*  reg_w    = (const float*)d_in[3];   // [14,256]
    const float*  reg_b    = (const float*)d_in[4];   // [14]
    const float*  psm_v2x  = (const float*)d_in[5];   // [4,20000]
    const float*  rm_v2x   = (const float*)d_in[6];   // [4,140000]
    const float*  scores   = (const float*)d_in[7];   // [4,20000]
    const int*    mask_idx = (const int*)d_in[8];     // [4,20000]
    // d_in[9] = mask_reg_idx: derivable (f + r*A*H*W), unused.
    float* out = (float*)d_out;

    // zero the winner table via a graph memset node (no kernel launch cost)
    void* slots_ptr = nullptr;
    cudaGetSymbolAddress(&slots_ptr, g_slots);
    cudaMemsetAsync(slots_ptr, 0, NSLOT * sizeof(unsigned long long));

    k_scatter<<<(NC_NUM * K_SEL + 255) / 256, 256>>>(mask_idx, scores);

    k_main<<<HW / PX_PER_BLK, 256>>>(feat, cls_w, cls_b, reg_w, reg_b,
                                     psm_v2x, rm_v2x, out);
}

// round 12
// speedup vs baseline: 1.5783x; 1.5783x over previous
#include <cuda_runtime.h>

// ---------------- problem constants ----------------
#define C_CH   256
#define H_BEV  200
#define W_BEV  704
#define HW     (H_BEV * W_BEV)     // 140800
#define A_NUM  2
#define NC_NUM 4
#define K_SEL  20000
#define NSLOT  (A_NUM * HW)        // 281600 flat A*H*W cells
#define RM_OFF NSLOT               // rm starts after psm in d_out
#define NOUT16 16                  // 2 cls + 14 reg channels
#define PX_BLK 256                 // pixels per block
#define THREADS 128                // 2 px per thread
#define CHUNK  16                  // channels per pipeline stage
#define NCHUNK (C_CH / CHUNK)      // 16

// packed winner table: high32 = float bits of peer score (positive -> monotonic),
// low32 = ((3 - cav_idx) << 16) | k.  0 == no peer selected this cell.
__device__ __align__(16) unsigned long long g_slots[NSLOT];

// ---------------- f32x2 helpers ----------------
__device__ __forceinline__ unsigned long long pack2(float lo, float hi) {
    unsigned long long r;
    asm("mov.b64 %0, {%1, %2};" : "=l"(r) : "f"(lo), "f"(hi));
    return r;
}
__device__ __forceinline__ void unpack2(unsigned long long v, float& lo, float& hi) {
    asm("mov.b64 {%0, %1}, %2;" : "=f"(lo), "=f"(hi) : "l"(v));
}
__device__ __forceinline__ unsigned long long fma2(unsigned long long a,
                                                   unsigned long long b,
                                                   unsigned long long c) {
    asm("fma.rn.f32x2 %0, %1, %2, %3;" : "=l"(c) : "l"(a), "l"(b), "l"(c));
    return c;
}
__device__ __forceinline__ void cp_async16(unsigned smem_dst, const void* gsrc) {
    asm volatile("cp.async.cg.shared.global [%0], [%1], 16;\n"
                 :: "r"(smem_dst), "l"(gsrc));
}

// ---------------- kernel 1: scatter peer candidates ----------------
__global__ void k_scatter(const int* __restrict__ mask_idx,
                          const float* __restrict__ scores) {
    int t = blockIdx.x * blockDim.x + threadIdx.x;
    if (t >= NC_NUM * K_SEL) return;
    int i = t / K_SEL;
    int k = t - i * K_SEL;                       // k < 20000 < 2^16
    int f = mask_idx[t];                         // flat index in [0, A*H*W)
    unsigned long long key =
        ((unsigned long long)__float_as_uint(scores[t]) << 32) |
        ((unsigned long long)(3 - i) << 16) | (unsigned)k;
    atomicMax(&g_slots[f], key);
}

// ---------------- kernel 2: cp.async-pipelined heads + select + gather -----
// 128 threads x 2 px = 256 pixels per block; grid = 550 exactly.
__global__ __launch_bounds__(THREADS)
void k_main(const float*  __restrict__ feat,     // [C, HW] f32
            const float*  __restrict__ cls_w,    // [2, 256]
            const float*  __restrict__ cls_b,    // [2]
            const float*  __restrict__ reg_w,    // [14, 256]
            const float*  __restrict__ reg_b,    // [14]
            const float*  __restrict__ psm_v2x,  // [4, 20000]
            const float*  __restrict__ rm_v2x,   // [4, 7*20000]
            float*        __restrict__ out) {    // [psm 281600 | rm 1971200]
    // weights stored once as f32x2 output-pairs: w2v[c][g].x = (w_{4g},w_{4g+1}),
    // .y = (w_{4g+2},w_{4g+3}).  One broadcast LDS.128 feeds 4 outputs.
    __shared__ __align__(16) ulonglong2 w2v[C_CH][NOUT16 / 4];   // 16384 B
    __shared__ __align__(16) float fbuf[2][CHUNK][PX_BLK];       // 32768 B
    // total static smem = 49152 B

    const int tid    = threadIdx.x;
    const int pxBase = blockIdx.x * PX_BLK;
    const int lane64 = tid & 63;          // 16B segment within a 1KB row
    const int rrow   = tid >> 6;          // starting row (0/1), stride 2

    unsigned fbuf_s = (unsigned)__cvta_generic_to_shared(&fbuf[0][0][0]);

    // ---- prologue: start chunks 0 and 1 flying first ----
#pragma unroll
    for (int b = 0; b < 2; ++b) {
        for (int r = rrow; r < CHUNK; r += 2)
            cp_async16(fbuf_s + (unsigned)(b * CHUNK + r) * (PX_BLK * 4) + lane64 * 16,
                       feat + (size_t)(b * CHUNK + r) * HW + pxBase + lane64 * 4);
        asm volatile("cp.async.commit_group;\n");
    }

    // ---- weight fill overlaps with the first copies ----
    for (int idx = tid; idx < C_CH * (NOUT16 / 2); idx += THREADS) {
        int c = idx >> 3, h = idx & 7;           // h = output-pair index 0..7
        int o0 = 2 * h, o1 = 2 * h + 1;
        float w0 = (o0 < A_NUM) ? cls_w[o0 * C_CH + c] : reg_w[(o0 - A_NUM) * C_CH + c];
        float w1 = (o1 < A_NUM) ? cls_w[o1 * C_CH + c] : reg_w[(o1 - A_NUM) * C_CH + c];
        ((unsigned long long*)&w2v[c][0])[h] = pack2(w0, w1);
    }

    unsigned long long a0[NOUT16 / 2], a1[NOUT16 / 2];   // per-pixel accs
#pragma unroll
    for (int h = 0; h < NOUT16 / 2; ++h) { a0[h] = 0ULL; a1[h] = 0ULL; }

    const int pi = tid;                  // pixel-pair slot: pixels 2*pi, 2*pi+1

    // ---- main pipeline: compute chunk k, copy chunk k+2 ----
    for (int k = 0; k < NCHUNK; ++k) {
        int buf = k & 1;
        asm volatile("cp.async.wait_group 1;\n");   // chunk k landed
        __syncthreads();

        const ulonglong2* wp = &w2v[k * CHUNK][0];
#pragma unroll
        for (int c = 0; c < CHUNK; ++c) {
            float2 x = *(const float2*)&fbuf[buf][c][2 * pi];  // LDS.64, 0-conflict
            unsigned long long xs0 = pack2(x.x, x.x);
            unsigned long long xs1 = pack2(x.y, x.y);
#pragma unroll
            for (int g = 0; g < NOUT16 / 4; ++g) {
                ulonglong2 w = wp[g];                          // broadcast LDS.128
                a0[2 * g]     = fma2(xs0, w.x, a0[2 * g]);
                a0[2 * g + 1] = fma2(xs0, w.y, a0[2 * g + 1]);
                a1[2 * g]     = fma2(xs1, w.x, a1[2 * g]);
                a1[2 * g + 1] = fma2(xs1, w.y, a1[2 * g + 1]);
            }
            wp += NOUT16 / 4;
        }
        __syncthreads();                 // everyone done reading buf before reuse

        int nk = k + 2;
        if (nk < NCHUNK) {
            for (int r = rrow; r < CHUNK; r += 2)
                cp_async16(fbuf_s + (unsigned)(buf * CHUNK + r) * (PX_BLK * 4) + lane64 * 16,
                           feat + (size_t)(nk * CHUNK + r) * HW + pxBase + lane64 * 4);
        }
        asm volatile("cp.async.commit_group;\n");   // keep group count in step
    }

    float v[NOUT16][2];
#pragma unroll
    for (int h = 0; h < NOUT16 / 2; ++h) {
        unpack2(a0[h], v[2 * h][0], v[2 * h + 1][0]);
        unpack2(a1[h], v[2 * h][1], v[2 * h + 1][1]);
    }

    int p = pxBase + 2 * pi;
#pragma unroll
    for (int a = 0; a < A_NUM; ++a) {
        float cb = cls_b[a];
        // slot pair for this anchor's two pixels (16B aligned: p even)
        ulonglong2 keys = *(const ulonglong2*)&g_slots[a * HW + p];

        bool  peer[2];
        int   ci[2], ck[2];
        float psm_o[2];
#pragma unroll
        for (int j = 0; j < 2; ++j) {
            float psm_ego = v[a][j] + cb;
            float prob    = 1.0f / (1.0f + expf(-psm_ego));  // sigmoid, fp32
            unsigned long long key = (j == 0) ? keys.x : keys.y;
            peer[j] = false; ci[j] = 0; ck[j] = 0;
            if (key != 0ULL) {
                float s = __uint_as_float((unsigned)(key >> 32));
                if (s > prob) {              // strict >: ego wins ties (argmax first-max)
                    peer[j] = true;
                    unsigned lo = (unsigned)key;
                    ck[j] = (int)(lo & 0xFFFFu);
                    ci[j] = 3 - (int)((lo >> 16) & 0xFFFFu);
                }
            }
            psm_o[j] = peer[j] ? psm_v2x[ci[j] * K_SEL + ck[j]] : psm_ego;
        }
        *(float2*)&out[a * HW + p] = make_float2(psm_o[0], psm_o[1]);

#pragma unroll
        for (int r = 0; r < 7; ++r) {
            int rc = 2 * r + a;              // rm channel using anchor-a winner
            float rb = reg_b[rc];
            float r0 = peer[0] ? rm_v2x[(ci[0] * 7 + r) * K_SEL + ck[0]]
                               : v[A_NUM + rc][0] + rb;
            float r1 = peer[1] ? rm_v2x[(ci[1] * 7 + r) * K_SEL + ck[1]]
                               : v[A_NUM + rc][1] + rb;
            *(float2*)&out[RM_OFF + rc * HW + p] = make_float2(r0, r1);
        }
    }
}

// ---------------- launch ----------------
extern "C" void kernel_launch(void* const* d_in, const int* in_sizes, int n_in,
                              void* d_out, int out_size) {
    const float*  feat     = (const float*)d_in[0];   // [1,256,200,704] f32
    const float*  cls_w    = (const float*)d_in[1];   // [2,256]
    const float*  cls_b    = (const float*)d_in[2];   // [2]
    const float*  reg_w    = (const float*)d_in[3];   // [14,256]
    const float*  reg_b    = (const float*)d_in[4];   // [14]
    const float*  psm_v2x  = (const float*)d_in[5];   // [4,20000]
    const float*  rm_v2x   = (const float*)d_in[6];   // [4,140000]
    const float*  scores   = (const float*)d_in[7];   // [4,20000]
    const int*    mask_idx = (const int*)d_in[8];     // [4,20000]
    // d_in[9] = mask_reg_idx: derivable (f + r*A*H*W), unused.
    float* out = (float*)d_out;

    // zero the winner table via a graph memset node (no kernel launch cost)
    void* slots_ptr = nullptr;
    cudaGetSymbolAddress(&slots_ptr, g_slots);
    cudaMemsetAsync(slots_ptr, 0, NSLOT * sizeof(unsigned long long));

    k_scatter<<<(NC_NUM * K_SEL + 255) / 256, 256>>>(mask_idx, scores);

    k_main<<<HW / PX_BLK, THREADS>>>(feat, cls_w, cls_b, reg_w, reg_b,
                                     psm_v2x, rm_v2x, out);
}